// round 9
// baseline (speedup 1.0000x reference)
#include <cuda_runtime.h>
#include <math.h>

#define VOCAB   50257
#define DIM     512
#define MAXDEP  20
#define NTOK    8192            // B*S
#define WPB     4               // warps (tokens) per 128-thread block
#define NBLOCK  (NTOK / WPB)    // 2048 blocks

__device__ float        g_partials[NBLOCK];
__device__ unsigned int g_count = 0;   // self-resets -> graph-replay safe

__global__ void __launch_bounds__(128) hs_kernel(
    const float* __restrict__ hidden,      // [NTOK, DIM]
    const float* __restrict__ node_emb,    // [VOCAB-1, DIM]
    const float* __restrict__ path_signs,  // [VOCAB, MAXDEP]
    const int*   __restrict__ targets,     // [NTOK]
    const int*   __restrict__ path_nodes,  // [VOCAB, MAXDEP]
    const int*   __restrict__ path_lens,   // [VOCAB]
    float*       __restrict__ out)
{
    __shared__ float s_warp[WPB];

    const int warp = threadIdx.x >> 5;
    const int lane = threadIdx.x & 31;
    const int tok  = blockIdx.x * WPB + warp;

    const int t   = targets[tok];
    int       len = path_lens[t];
    if (len < 1) len = 1;

    // Coalesced preload of path metadata; broadcast via shfl at use sites.
    int   my_node = 0;
    float my_sign = 1.0f;
    if (lane < MAXDEP) {
        my_node = path_nodes[(size_t)t * MAXDEP + lane];
        my_sign = (path_signs[(size_t)t * MAXDEP + lane] >= 0.0f) ? 1.0f : -1.0f;
    }

    // Hidden row: 16 floats/lane in registers.
    const float4* h4 = reinterpret_cast<const float4*>(hidden + (size_t)tok * DIM);
    const float4 h0 = h4[lane];
    const float4 h1 = h4[lane + 32];
    const float4 h2 = h4[lane + 64];
    const float4 h3 = h4[lane + 96];

    // Three row buffers cycled with compile-time indices (no rotation movs).
    float4 b[3][4];

    // ---- Prologue: rows 0 and 1 in flight before the loop.
    {
        const int n0 = __shfl_sync(0xffffffffu, my_node, 0);
        const float4* w4 = reinterpret_cast<const float4*>(node_emb + (size_t)n0 * DIM);
        b[0][0] = w4[lane];      b[0][1] = w4[lane + 32];
        b[0][2] = w4[lane + 64]; b[0][3] = w4[lane + 96];
    }
    {
        const int d1 = (1 < len) ? 1 : (len - 1);
        const int n1 = __shfl_sync(0xffffffffu, my_node, d1);
        const float4* w4 = reinterpret_cast<const float4*>(node_emb + (size_t)n1 * DIM);
        b[1][0] = w4[lane];      b[1][1] = w4[lane + 32];
        b[1][2] = w4[lane + 64]; b[1][3] = w4[lane + 96];
    }

    float nll = 0.0f;

    // ---- Fully-unrolled 3-deep pipeline: prefetch d+2 while computing d.
    #pragma unroll
    for (int d = 0; d < MAXDEP; ++d) {
        if (d >= len) break;   // warp-uniform

        // Prefetch row d+2 into the free slot (clamped -> L1-hot when past end).
        {
            const int dn   = (d + 2 < len) ? (d + 2) : (len - 1);
            const int node = __shfl_sync(0xffffffffu, my_node, dn);
            const float4* w4 =
                reinterpret_cast<const float4*>(node_emb + (size_t)node * DIM);
            b[(d + 2) % 3][0] = w4[lane];
            b[(d + 2) % 3][1] = w4[lane + 32];
            b[(d + 2) % 3][2] = w4[lane + 64];
            b[(d + 2) % 3][3] = w4[lane + 96];
        }

        // Compute with row d (its loads were issued two iterations ago).
        const float4 c0 = b[d % 3][0];
        const float4 c1 = b[d % 3][1];
        const float4 c2 = b[d % 3][2];
        const float4 c3 = b[d % 3][3];

        float a;
        a = h0.x * c0.x;           a = fmaf(h0.y, c0.y, a);
        a = fmaf(h0.z, c0.z, a);   a = fmaf(h0.w, c0.w, a);
        a = fmaf(h1.x, c1.x, a);   a = fmaf(h1.y, c1.y, a);
        a = fmaf(h1.z, c1.z, a);   a = fmaf(h1.w, c1.w, a);
        a = fmaf(h2.x, c2.x, a);   a = fmaf(h2.y, c2.y, a);
        a = fmaf(h2.z, c2.z, a);   a = fmaf(h2.w, c2.w, a);
        a = fmaf(h3.x, c3.x, a);   a = fmaf(h3.y, c3.y, a);
        a = fmaf(h3.z, c3.z, a);   a = fmaf(h3.w, c3.w, a);

        #pragma unroll
        for (int off = 16; off > 0; off >>= 1)
            a += __shfl_xor_sync(0xffffffffu, a, off);

        const float sgn = __shfl_sync(0xffffffffu, my_sign, d);
        const float z   = sgn * a;
        // -log sigmoid(z) = max(-z,0) + log1p(exp(-|z|))   (stable)
        nll += fmaxf(-z, 0.0f) + log1pf(expf(-fabsf(z)));
    }

    if (lane == 0) s_warp[warp] = nll;
    __syncthreads();

    if (threadIdx.x == 0) {
        float bs = 0.0f;
        #pragma unroll
        for (int i = 0; i < WPB; ++i) bs += s_warp[i];
        g_partials[blockIdx.x] = bs;
    }
    __threadfence();

    // Last-block-done: one block deterministically reduces all partials.
    __shared__ unsigned int s_last;
    if (threadIdx.x == 0)
        s_last = (atomicAdd(&g_count, 1u) == (unsigned)(gridDim.x - 1));
    __syncthreads();

    if (s_last) {
        float s = 0.0f;
        #pragma unroll
        for (int i = 0; i < NBLOCK / 128; ++i)
            s += g_partials[threadIdx.x + i * 128];

        __shared__ float sm[128];
        sm[threadIdx.x] = s;
        __syncthreads();
        #pragma unroll
        for (int k = 64; k > 0; k >>= 1) {
            if (threadIdx.x < k) sm[threadIdx.x] += sm[threadIdx.x + k];
            __syncthreads();
        }
        if (threadIdx.x == 0) {
            out[0]  = sm[0] * (1.0f / (float)NTOK);
            g_count = 0;   // reset for next launch / graph replay
        }
    }
}

extern "C" void kernel_launch(void* const* d_in, const int* in_sizes, int n_in,
                              void* d_out, int out_size)
{
    const float* hidden     = (const float*)d_in[0];
    const float* node_emb   = (const float*)d_in[1];
    const float* path_signs = (const float*)d_in[2];
    const int*   targets    = (const int*)  d_in[3];
    const int*   path_nodes = (const int*)  d_in[4];
    const int*   path_lens  = (const int*)  d_in[5];
    float*       out        = (float*)d_out;

    hs_kernel<<<NBLOCK, 128>>>(hidden, node_emb, path_signs,
                               targets, path_nodes, path_lens, out);
}